// round 13
// baseline (speedup 1.0000x reference)
#include <cuda_runtime.h>
#include <cuda_bf16.h>
#include <math.h>
#include <stdint.h>

#define NV 6890
#define MP 6912
#define CIN 3
#define RR 5
#define AA 8
#define TT 100
#define NSLOT 11
#define SLOTA 1024                 // A slot stride: [Ah | Al], each padded to 512
#define LDAF (NSLOT * SLOTA)       // 11264
#define LDCF 1408                  // g_cf row stride (floats)
#define LDAX 320
#define LDBD 6912
#define KT_DENSE 320
// B regions (elems): layer0 11*3*64*128, layers1/2 11*3*512*128 each
#define OB0 0
#define OB1 270336
#define OB2 2433024
#define BTOT 4595712

// ---- scratch (device globals, zero-initialized at module load) ----
__device__ float g_x[NV * TT];
__device__ __nv_bfloat16 g_A [(size_t)MP * LDAF];
__device__ __nv_bfloat16 g_B [BTOT];
__device__ __nv_bfloat16 g_Ax[(size_t)MP * LDAX];
__device__ __nv_bfloat16 g_Bd[(size_t)KT_DENSE * LDBD];
__device__ float g_cf[(size_t)NV * LDCF];

__device__ __forceinline__ void bfsplit(float f, __nv_bfloat16& hi, __nv_bfloat16& lo) {
    hi = __float2bfloat16(f);
    lo = __float2bfloat16(f - __bfloat162float(hi));
}
__device__ __forceinline__ uint32_t sptr(const void* p) {
    return (uint32_t)__cvta_generic_to_shared(p);
}

#define SQH 0.70710678118654752f

// ---- 8-pt DFT: p[8] -> f0, f4, (re,im) for f=1,2,3 ----
__device__ __forceinline__ void dft8(const float* p, float& f0, float& f4,
                                     float* re, float* im) {
    float s07 = p[1] - p[3] - p[5] + p[7];
    float s25 = p[1] + p[3] - p[5] - p[7];
    float s16 = p[2] - p[6];
    float d04 = p[0] - p[4];
    f0 = p[0]+p[1]+p[2]+p[3]+p[4]+p[5]+p[6]+p[7];
    f4 = p[0]-p[1]+p[2]-p[3]+p[4]-p[5]+p[6]-p[7];
    re[0] = d04 + SQH * s07;        im[0] = -(SQH * s25 + s16);
    re[1] = p[0]-p[2]+p[4]-p[6];    im[1] = -(p[1]-p[3]+p[5]-p[7]);
    re[2] = d04 - SQH * s07;        im[2] = s16 - SQH * s25;
}

// ---- weight DFT -> B slot rows [Bh @k | Bl @HB+k | Bh @2HB+k], Karatsuba combos ----
__device__ void buildB_dev(const float* __restrict__ W, int C,
                           __nv_bfloat16* __restrict__ Bb, int HB, int e) {
    int tot = TT * RR * C;
    if (e >= tot) return;
    int t = e / (RR * C);
    int rc = e % (RR * C);
    int r = rc / C, c = rc % C;
    float p[8];
#pragma unroll
    for (int a = 0; a < 8; a++)
        p[a] = W[(((size_t)t * RR + r) * AA + a) * C + c];
    float f0, f4, re[3], im[3];
    dft8(p, f0, f4, re, im);
    int k = r * C + c;
    int slotSz = 3 * HB * 128;
    __nv_bfloat16 hi, lo;
#define STB(s, val) { bfsplit((val), hi, lo); \
    __nv_bfloat16* b_ = Bb + (size_t)(s) * slotSz + t; \
    b_[(size_t)k * 128] = hi; b_[(size_t)(HB + k) * 128] = lo; \
    b_[(size_t)(2 * HB + k) * 128] = hi; }
    STB(0, f0); STB(1, f4);
#pragma unroll
    for (int j = 0; j < 3; j++) {
        int s = 2 + 3 * j;
        STB(s,     re[j]);           // pairs with p1 = Pr - Pi
        STB(s + 1, im[j] - re[j]);   // pairs with p2 = Pr
        STB(s + 2, re[j] + im[j]);   // pairs with p3 = Pi
    }
#undef STB
}

// ---- fused init: normalize + B DFT (3 layers) + dense B, one launch ----
__global__ void k_init(const float* __restrict__ sig, const float* __restrict__ mean,
                       const float* __restrict__ var,
                       const float* __restrict__ w0, const float* __restrict__ w1,
                       const float* __restrict__ w2, const float* __restrict__ dw) {
    int b = blockIdx.x, tid = threadIdx.x;
    if (b < 81) {
        int i = b * 256 + tid;
        if (i < NV * CIN) {
            int c = i % CIN;
            g_x[i] = (sig[i] - mean[c]) * rsqrtf(var[c]);
        }
    } else if (b < 87) {
        buildB_dev(w0, CIN, g_B + OB0, 64,  (b - 81) * 256 + tid);
    } else if (b < 283) {
        buildB_dev(w1, TT,  g_B + OB1, 512, (b - 87) * 256 + tid);
    } else if (b < 479) {
        buildB_dev(w2, TT,  g_B + OB2, 512, (b - 283) * 256 + tid);
    } else {
        int e = (b - 479) * 256 + tid;
        if (e < TT * NV) {
            int k = e / NV, n = e % NV;
            __nv_bfloat16 hi, lo; bfsplit(dw[e], hi, lo);
            g_Bd[(size_t)k * LDBD + n] = hi;
            g_Bd[(size_t)(TT + k) * LDBD + n] = lo;
            g_Bd[(size_t)(2 * TT + k) * LDBD + n] = hi;
        }
    }
}

// ---- patch gather + DFT + Karatsuba parts -> 11 A slots [Ah(512)|Al(512)] ----
__global__ void k_patch_fft(const int* __restrict__ idx,
                            const float* __restrict__ w, int C, int HB) {
    __shared__ int   sI[8][24];
    __shared__ float sW[8][24];
    int warp = threadIdx.x >> 5, lane = threadIdx.x & 31;
    int gw = blockIdx.x * 8 + warp;
    if (gw >= NV * RR) return;
    int v = gw / RR, r = gw % RR;
    if (lane < 24) {
        sI[warp][lane] = idx[gw * 24 + lane];
        sW[warp][lane] = w[gw * 24 + lane];
    }
    __syncwarp();

    int K1 = RR * C;
    __nv_bfloat16* row = g_A + (size_t)v * LDAF;

    for (int c = lane; c < C; c += 32) {
        float p[8];
#pragma unroll
        for (int a = 0; a < 8; a++) {
            p[a] = sW[warp][a*3+0] * g_x[sI[warp][a*3+0] * C + c]
                 + sW[warp][a*3+1] * g_x[sI[warp][a*3+1] * C + c]
                 + sW[warp][a*3+2] * g_x[sI[warp][a*3+2] * C + c];
        }
        float f0, f4, re[3], im[3];
        dft8(p, f0, f4, re, im);
        int k = r * C + c;
        __nv_bfloat16 hi, lo;
#define STA(s, val) { bfsplit((val), hi, lo); \
        __nv_bfloat16* a_ = row + (s) * SLOTA; \
        a_[k] = hi; a_[HB + k] = lo; }
        STA(0, f0); STA(1, f4);
#pragma unroll
        for (int j = 0; j < 3; j++) {
            int s = 2 + 3 * j;
            STA(s,     re[j] - im[j]);
            STA(s + 1, re[j]);
            STA(s + 2, im[j]);
        }
#undef STA
    }
    if (r == 0) {   // zero pads [K1,HB) in both blocks
        __nv_bfloat16 z = __float2bfloat16(0.f);
        for (int e = K1 + lane; e < HB; e += 32)
#pragma unroll
            for (int s = 0; s < NSLOT; s++) {
                row[s * SLOTA + e] = z;
                row[s * SLOTA + HB + e] = z;
            }
    }
}

// ======== GEMM engine: 192x128x64, 512 threads (16 warps 4x4), warp 48x32,
// ======== 3-stage cp.async ring, fragment double-buffer, 1 CTA/SM ========
#define ASTG 24576   // 192 rows x 128B
#define BSTG 16384   // 64 rows x 256B
#define STGSZ (ASTG + BSTG)

// ---- per-slot conv GEMM: logical K' = 3*HB, A chunks walk [Ah, Ah, Al] ----
__global__ void __launch_bounds__(512, 1)
k_gemm_f(const __nv_bfloat16* __restrict__ Ab, const __nv_bfloat16* __restrict__ Bb,
         float* __restrict__ Cb, int nh) {
    extern __shared__ char smem[];
    int sx = blockIdx.x;
    const __nv_bfloat16* A = Ab + sx * SLOTA;
    const __nv_bfloat16* B = Bb + (size_t)sx * (3 * nh * 64) * 128;

    int tid = threadIdx.x;
    int bm = blockIdx.y * 192;
    int warp = tid >> 5, lane = tid & 31;
    int wm = (warp >> 2) * 48, wn = (warp & 3) * 32;

    float acc[3][4][4];
#pragma unroll
    for (int i = 0; i < 3; i++)
#pragma unroll
        for (int j = 0; j < 4; j++)
#pragma unroll
            for (int q = 0; q < 4; q++) acc[i][j][q] = 0.f;

    auto aoffOf = [&](int c) { return ((c < nh) ? c : c - nh) * 64; };

    auto copyA = [&](int stage, int chunk) {
        char* base = smem + stage * STGSZ;
        int k0 = aoffOf(chunk);
#pragma unroll
        for (int j = 0; j < 3; j++) {        // 192 rows x 8 units = 1536 = 3*512
            int idx2 = tid + 512 * j;
            int r = idx2 >> 3, u = idx2 & 7;
            int su = u ^ (r & 7);
            const __nv_bfloat16* src = A + (size_t)(bm + r) * LDAF + k0 + u * 8;
            asm volatile("cp.async.cg.shared.global [%0], [%1], 16;"
                         :: "r"(sptr(base + r * 128 + su * 16)), "l"(src));
        }
    };
    auto copyB = [&](int stage, int chunk) {
        char* base = smem + stage * STGSZ + ASTG;
        int k0 = chunk * 64;
#pragma unroll
        for (int j = 0; j < 2; j++) {        // 64 rows x 16 units = 1024 = 2*512
            int idx2 = tid + 512 * j;
            int r = idx2 >> 4, u = idx2 & 15;
            int su = (u & 8) | ((u ^ r) & 7);
            const __nv_bfloat16* src = B + (size_t)(k0 + r) * 128 + u * 8;
            asm volatile("cp.async.cg.shared.global [%0], [%1], 16;"
                         :: "r"(sptr(base + r * 256 + su * 16)), "l"(src));
        }
    };

    int niter = 3 * nh;
    copyA(0, 0);  copyB(0, 0);
    asm volatile("cp.async.commit_group;");
    copyA(1, 1);  copyB(1, 1);
    asm volatile("cp.async.commit_group;");

    int q = lane >> 3, rr = lane & 7;
    uint32_t af[2][3][4], bf2[2][4][2];

    auto ldfrag = [&](const char* sA, const char* sB, int ks, int b) {
#pragma unroll
        for (int mt = 0; mt < 3; mt++) {
            int m_loc = wm + mt * 16 + (q & 1) * 8 + rr;
            int unit = ks * 2 + (q >> 1);
            int su = unit ^ (m_loc & 7);
            asm volatile("ldmatrix.sync.aligned.m8n8.x4.shared.b16 {%0,%1,%2,%3}, [%4];"
                         : "=r"(af[b][mt][0]), "=r"(af[b][mt][1]),
                           "=r"(af[b][mt][2]), "=r"(af[b][mt][3])
                         : "r"(sptr(sA + m_loc * 128 + su * 16)));
        }
#pragma unroll
        for (int ntp = 0; ntp < 2; ntp++) {
            int k_loc = ks * 16 + (q & 1) * 8 + rr;
            int unit = (wn >> 3) + ntp * 2 + (q >> 1);
            int su = (unit & 8) | ((unit ^ k_loc) & 7);
            asm volatile("ldmatrix.sync.aligned.m8n8.x4.trans.shared.b16 {%0,%1,%2,%3}, [%4];"
                         : "=r"(bf2[b][2 * ntp][0]), "=r"(bf2[b][2 * ntp][1]),
                           "=r"(bf2[b][2 * ntp + 1][0]), "=r"(bf2[b][2 * ntp + 1][1])
                         : "r"(sptr(sB + k_loc * 256 + su * 16)));
        }
    };

    for (int i = 0; i < niter; i++) {
        asm volatile("cp.async.wait_group 1;");
        __syncthreads();
        int pf = i + 2;
        if (pf < niter) {
            int st2 = pf % 3;
            copyA(st2, pf); copyB(st2, pf);
        }
        asm volatile("cp.async.commit_group;");

        int stg = i % 3;
        const char* sA = smem + stg * STGSZ;
        const char* sB = smem + stg * STGSZ + ASTG;
        ldfrag(sA, sB, 0, 0);
#pragma unroll
        for (int ks = 0; ks < 4; ks++) {
            int cur = ks & 1;
            if (ks < 3) ldfrag(sA, sB, ks + 1, cur ^ 1);
#pragma unroll
            for (int mt = 0; mt < 3; mt++)
#pragma unroll
                for (int nt = 0; nt < 4; nt++) {
                    asm volatile(
                        "mma.sync.aligned.m16n8k16.row.col.f32.bf16.bf16.f32 "
                        "{%0,%1,%2,%3}, {%4,%5,%6,%7}, {%8,%9}, {%0,%1,%2,%3};"
                        : "+f"(acc[mt][nt][0]), "+f"(acc[mt][nt][1]),
                          "+f"(acc[mt][nt][2]), "+f"(acc[mt][nt][3])
                        : "r"(af[cur][mt][0]), "r"(af[cur][mt][1]),
                          "r"(af[cur][mt][2]), "r"(af[cur][mt][3]),
                          "r"(bf2[cur][nt][0]), "r"(bf2[cur][nt][1]));
                }
        }
    }

    int g = lane >> 2, t4 = lane & 3;
    int coff = sx * 128;
#pragma unroll
    for (int mt = 0; mt < 3; mt++) {
#pragma unroll
        for (int nt = 0; nt < 4; nt++) {
            int lcol = wn + nt * 8 + 2 * t4;
            if (lcol >= TT) continue;
            int row0 = bm + wm + mt * 16 + g;
#pragma unroll
            for (int h = 0; h < 2; h++) {
                int r = row0 + h * 8;
                if (r >= NV) continue;
                *reinterpret_cast<float2*>(Cb + (size_t)r * LDCF + coff + lcol) =
                    make_float2(acc[mt][nt][h * 2 + 0], acc[mt][nt][h * 2 + 1]);
            }
        }
    }
}

// ---- dense GEMM (bias), same 192x128 engine ----
__global__ void __launch_bounds__(512, 1)
k_gemm(const __nv_bfloat16* __restrict__ A, int lda,
       const __nv_bfloat16* __restrict__ B, int ldb,
       const float* __restrict__ bias, int biasMod,
       float* __restrict__ C, int ldc, int M, int N, int KT) {
    extern __shared__ char smem[];
    __shared__ float sbias[128];
    int tid = threadIdx.x;
    int bm = blockIdx.y * 192, bn = blockIdx.x * 128;
    int warp = tid >> 5, lane = tid & 31;
    int wm = (warp >> 2) * 48, wn = (warp & 3) * 32;
    if (tid < 128) sbias[tid] = bias[(bn + tid) % biasMod];

    float acc[3][4][4];
#pragma unroll
    for (int i = 0; i < 3; i++)
#pragma unroll
        for (int j = 0; j < 4; j++)
#pragma unroll
            for (int q = 0; q < 4; q++) acc[i][j][q] = 0.f;

    auto copyA = [&](int stage, int k0) {
        char* base = smem + stage * STGSZ;
#pragma unroll
        for (int j = 0; j < 3; j++) {
            int idx2 = tid + 512 * j;
            int r = idx2 >> 3, u = idx2 & 7;
            int su = u ^ (r & 7);
            const __nv_bfloat16* src = A + (size_t)(bm + r) * lda + k0 + u * 8;
            asm volatile("cp.async.cg.shared.global [%0], [%1], 16;"
                         :: "r"(sptr(base + r * 128 + su * 16)), "l"(src));
        }
    };
    auto copyB = [&](int stage, int k0) {
        char* base = smem + stage * STGSZ + ASTG;
#pragma unroll
        for (int j = 0; j < 2; j++) {
            int idx2 = tid + 512 * j;
            int r = idx2 >> 4, u = idx2 & 15;
            int su = (u & 8) | ((u ^ r) & 7);
            const __nv_bfloat16* src = B + (size_t)(k0 + r) * ldb + bn + u * 8;
            asm volatile("cp.async.cg.shared.global [%0], [%1], 16;"
                         :: "r"(sptr(base + r * 256 + su * 16)), "l"(src));
        }
    };

    int niter = KT >> 6;
    copyA(0, 0);  copyB(0, 0);
    asm volatile("cp.async.commit_group;");
    copyA(1, 64); copyB(1, 64);
    asm volatile("cp.async.commit_group;");

    int q = lane >> 3, rr = lane & 7;
    uint32_t af[2][3][4], bf2[2][4][2];
    auto ldfrag = [&](const char* sA, const char* sB, int ks, int b) {
#pragma unroll
        for (int mt = 0; mt < 3; mt++) {
            int m_loc = wm + mt * 16 + (q & 1) * 8 + rr;
            int unit = ks * 2 + (q >> 1);
            int su = unit ^ (m_loc & 7);
            asm volatile("ldmatrix.sync.aligned.m8n8.x4.shared.b16 {%0,%1,%2,%3}, [%4];"
                         : "=r"(af[b][mt][0]), "=r"(af[b][mt][1]),
                           "=r"(af[b][mt][2]), "=r"(af[b][mt][3])
                         : "r"(sptr(sA + m_loc * 128 + su * 16)));
        }
#pragma unroll
        for (int ntp = 0; ntp < 2; ntp++) {
            int k_loc = ks * 16 + (q & 1) * 8 + rr;
            int unit = (wn >> 3) + ntp * 2 + (q >> 1);
            int su = (unit & 8) | ((unit ^ k_loc) & 7);
            asm volatile("ldmatrix.sync.aligned.m8n8.x4.trans.shared.b16 {%0,%1,%2,%3}, [%4];"
                         : "=r"(bf2[b][2 * ntp][0]), "=r"(bf2[b][2 * ntp][1]),
                           "=r"(bf2[b][2 * ntp + 1][0]), "=r"(bf2[b][2 * ntp + 1][1])
                         : "r"(sptr(sB + k_loc * 256 + su * 16)));
        }
    };

    for (int i = 0; i < niter; i++) {
        asm volatile("cp.async.wait_group 1;");
        __syncthreads();
        int pf = i + 2;
        if (pf < niter) {
            int st2 = pf % 3;
            copyA(st2, pf * 64); copyB(st2, pf * 64);
        }
        asm volatile("cp.async.commit_group;");
        int stg = i % 3;
        const char* sA = smem + stg * STGSZ;
        const char* sB = smem + stg * STGSZ + ASTG;
        ldfrag(sA, sB, 0, 0);
#pragma unroll
        for (int ks = 0; ks < 4; ks++) {
            int cur = ks & 1;
            if (ks < 3) ldfrag(sA, sB, ks + 1, cur ^ 1);
#pragma unroll
            for (int mt = 0; mt < 3; mt++)
#pragma unroll
                for (int nt = 0; nt < 4; nt++) {
                    asm volatile(
                        "mma.sync.aligned.m16n8k16.row.col.f32.bf16.bf16.f32 "
                        "{%0,%1,%2,%3}, {%4,%5,%6,%7}, {%8,%9}, {%0,%1,%2,%3};"
                        : "+f"(acc[mt][nt][0]), "+f"(acc[mt][nt][1]),
                          "+f"(acc[mt][nt][2]), "+f"(acc[mt][nt][3])
                        : "r"(af[cur][mt][0]), "r"(af[cur][mt][1]),
                          "r"(af[cur][mt][2]), "r"(af[cur][mt][3]),
                          "r"(bf2[cur][nt][0]), "r"(bf2[cur][nt][1]));
                }
        }
    }

    int g = lane >> 2, t4 = lane & 3;
#pragma unroll
    for (int mt = 0; mt < 3; mt++) {
#pragma unroll
        for (int nt = 0; nt < 4; nt++) {
            int lcol = wn + nt * 8 + 2 * t4;
            int col = bn + lcol;
            if (col >= N) continue;
            float b0 = sbias[lcol], b1 = sbias[lcol + 1];
            int row0 = bm + wm + mt * 16 + g;
#pragma unroll
            for (int h = 0; h < 2; h++) {
                int r = row0 + h * 8;
                if (r >= M) continue;
                *reinterpret_cast<float2*>(C + (size_t)r * ldc + col) =
                    make_float2(acc[mt][nt][h * 2 + 0] + b0, acc[mt][nt][h * 2 + 1] + b1);
            }
        }
    }
}

// ---- Karatsuba combine + IDFT + bias + relu + AMP + BN -> g_x, g_Ax ----
__device__ __constant__ float c_COS8[8] = {1.f, SQH, 0.f, -SQH, -1.f, -SQH, 0.f, SQH};
__device__ __constant__ float c_SIN8[8] = {0.f, SQH, 1.f, SQH, 0.f, -SQH, -1.f, -SQH};

__global__ void k_amp_fft(const float* __restrict__ bias,
                          const float* __restrict__ bn_g, const float* __restrict__ bn_b,
                          const float* __restrict__ bn_m, const float* __restrict__ bn_v,
                          int blk) {
    int v = blockIdx.x;
    int tid = threadIdx.x, lane = tid & 31, warp = tid >> 5;
    const float* row = g_cf + (size_t)v * LDCF;
    __shared__ float wsum[4][8];
    __shared__ int snbest;

    float y[8];
#pragma unroll
    for (int n = 0; n < 8; n++) y[n] = 0.f;
    if (tid < TT) {
        float c0 = row[tid], c4 = row[128 + tid];
        float Cr[3], Ci[3];
#pragma unroll
        for (int j = 0; j < 3; j++) {
            int base = (2 + 3 * j) * 128;
            float g1 = row[base + tid], g2 = row[base + 128 + tid], g3 = row[base + 256 + tid];
            Cr[j] = g1 + g3;
            Ci[j] = g1 + g2;
        }
        float b = bias[tid];
#pragma unroll
        for (int n = 0; n < 8; n++) {
            float s = c0 + ((n & 1) ? -c4 : c4)
                + 2.f * (Cr[0] * c_COS8[n & 7]     - Ci[0] * c_SIN8[n & 7]
                       + Cr[1] * c_COS8[(2*n) & 7] - Ci[1] * c_SIN8[(2*n) & 7]
                       + Cr[2] * c_COS8[(3*n) & 7] - Ci[2] * c_SIN8[(3*n) & 7]);
            y[n] = fmaxf(0.125f * s + b, 0.f);
        }
    }
    float sq[8];
#pragma unroll
    for (int n = 0; n < 8; n++) {
        sq[n] = y[n] * y[n];
#pragma unroll
        for (int o = 16; o; o >>= 1) sq[n] += __shfl_down_sync(0xffffffffu, sq[n], o);
    }
    if (lane == 0)
#pragma unroll
        for (int n = 0; n < 8; n++) wsum[warp][n] = sq[n];
    __syncthreads();
    if (tid == 0) {
        int best = 0; float bv = -1.f;
#pragma unroll
        for (int n = 0; n < 8; n++) {
            float s = wsum[0][n] + wsum[1][n] + wsum[2][n] + wsum[3][n];
            if (s > bv) { bv = s; best = n; }
        }
        snbest = best;
    }
    __syncthreads();
    if (tid < TT) {
        int b = snbest;
        float x = y[0];
#pragma unroll
        for (int n = 1; n < 8; n++) if (b == n) x = y[n];
        float gg = bn_g[blk * TT + tid], bb = bn_b[blk * TT + tid];
        float mm = bn_m[blk * TT + tid], va = bn_v[blk * TT + tid];
        float yy = gg * (x - mm) * rsqrtf(va + 1e-3f) + bb;
        g_x[(size_t)v * TT + tid] = yy;
        __nv_bfloat16 hi, lo; bfsplit(yy, hi, lo);
        __nv_bfloat16* arow = g_Ax + (size_t)v * LDAX;
        arow[tid] = hi; arow[TT + tid] = hi; arow[2 * TT + tid] = lo;
    }
}

extern "C" void kernel_launch(void* const* d_in, const int* in_sizes, int n_in,
                              void* d_out, int out_size) {
    const float* signal  = (const float*)d_in[0];
    const int*   bc_idx  = (const int*)  d_in[1];
    const float* bc_w    = (const float*)d_in[2];
    const float* nmean   = (const float*)d_in[3];
    const float* nvar    = (const float*)d_in[4];
    const float* w0      = (const float*)d_in[5];
    const float* b0      = (const float*)d_in[6];
    const float* w1      = (const float*)d_in[7];
    const float* b1      = (const float*)d_in[8];
    const float* w2      = (const float*)d_in[9];
    const float* b2      = (const float*)d_in[10];
    const float* bn_g    = (const float*)d_in[11];
    const float* bn_b    = (const float*)d_in[12];
    const float* bn_m    = (const float*)d_in[13];
    const float* bn_v    = (const float*)d_in[14];
    const float* dense_w = (const float*)d_in[15];
    const float* dense_b = (const float*)d_in[16];
    float* out = (float*)d_out;

    const int SMEM = 3 * STGSZ;   // 120KB
    cudaFuncSetAttribute(k_gemm_f, cudaFuncAttributeMaxDynamicSharedMemorySize, SMEM);
    cudaFuncSetAttribute(k_gemm,   cudaFuncAttributeMaxDynamicSharedMemorySize, SMEM);

    __nv_bfloat16 *p_A, *p_B, *p_Ax, *p_Bd;
    float *p_cf;
    cudaGetSymbolAddress((void**)&p_A, g_A);
    cudaGetSymbolAddress((void**)&p_B, g_B);
    cudaGetSymbolAddress((void**)&p_Ax, g_Ax);
    cudaGetSymbolAddress((void**)&p_Bd, g_Bd);
    cudaGetSymbolAddress((void**)&p_cf, g_cf);

    k_init<<<3171, 256>>>(signal, nmean, nvar, w0, w1, w2, dense_w);

    const float* bs[3] = {b0, b1, b2};
    const int    Cs[3] = {CIN, TT, TT};
    const int    HBs[3] = {64, 512, 512};
    const size_t OBs[3] = {OB0, OB1, OB2};

    for (int blk = 0; blk < 3; blk++) {
        k_patch_fft<<<(NV * RR + 7) / 8, 256>>>(bc_idx, bc_w, Cs[blk], HBs[blk]);
        k_gemm_f<<<dim3(NSLOT, MP / 192), 512, SMEM>>>(p_A, p_B + OBs[blk], p_cf, HBs[blk] / 64);
        k_amp_fft<<<NV, 128>>>(bs[blk], bn_g, bn_b, bn_m, bn_v, blk);
    }

    // dense head
    dim3 denseGrid(54, MP / 192);
    k_gemm<<<denseGrid, 512, SMEM>>>(p_Ax, LDAX, p_Bd, LDBD, dense_b, NV,
                                     out, NV, NV, NV, KT_DENSE);
}

// round 14
// speedup vs baseline: 1.0801x; 1.0801x over previous
#include <cuda_runtime.h>
#include <cuda_bf16.h>
#include <math.h>
#include <stdint.h>

#define NV 6890
#define MP 6912
#define CIN 3
#define RR 5
#define AA 8
#define TT 100
#define NSLOT 11
#define SLOTA 1024                 // A slot stride: [Ah | Al], each padded to 512
#define LDAF (NSLOT * SLOTA)       // 11264
#define LDCF 1104                  // g_cf row stride (floats): 11 slots x 100, +4 pad
#define LDAX 320
#define LDBD 6912
#define KT_DENSE 320
// B regions (elems): layer0 11*3*64*128, layers1/2 11*3*512*128 each
#define OB0 0
#define OB1 270336
#define OB2 2433024
#define BTOT 4595712

// ---- scratch (device globals, zero-initialized at module load) ----
__device__ float g_x[NV * TT];
__device__ __nv_bfloat16 g_A [(size_t)MP * LDAF];
__device__ __nv_bfloat16 g_B [BTOT];
__device__ __nv_bfloat16 g_Ax[(size_t)MP * LDAX];
__device__ __nv_bfloat16 g_Bd[(size_t)KT_DENSE * LDBD];
__device__ float g_cf[(size_t)NV * LDCF];

__device__ __forceinline__ void bfsplit(float f, __nv_bfloat16& hi, __nv_bfloat16& lo) {
    hi = __float2bfloat16(f);
    lo = __float2bfloat16(f - __bfloat162float(hi));
}
__device__ __forceinline__ uint32_t sptr(const void* p) {
    return (uint32_t)__cvta_generic_to_shared(p);
}

#define SQH 0.70710678118654752f

// ---- 8-pt DFT: p[8] -> f0, f4, (re,im) for f=1,2,3 ----
__device__ __forceinline__ void dft8(const float* p, float& f0, float& f4,
                                     float* re, float* im) {
    float s07 = p[1] - p[3] - p[5] + p[7];
    float s25 = p[1] + p[3] - p[5] - p[7];
    float s16 = p[2] - p[6];
    float d04 = p[0] - p[4];
    f0 = p[0]+p[1]+p[2]+p[3]+p[4]+p[5]+p[6]+p[7];
    f4 = p[0]-p[1]+p[2]-p[3]+p[4]-p[5]+p[6]-p[7];
    re[0] = d04 + SQH * s07;        im[0] = -(SQH * s25 + s16);
    re[1] = p[0]-p[2]+p[4]-p[6];    im[1] = -(p[1]-p[3]+p[5]-p[7]);
    re[2] = d04 - SQH * s07;        im[2] = s16 - SQH * s25;
}

// ---- weight DFT -> B slot rows [Bh @k | Bl @HB+k | Bh @2HB+k], Karatsuba combos ----
__device__ void buildB_dev(const float* __restrict__ W, int C,
                           __nv_bfloat16* __restrict__ Bb, int HB, int e) {
    int tot = TT * RR * C;
    if (e >= tot) return;
    int t = e / (RR * C);
    int rc = e % (RR * C);
    int r = rc / C, c = rc % C;
    float p[8];
#pragma unroll
    for (int a = 0; a < 8; a++)
        p[a] = W[(((size_t)t * RR + r) * AA + a) * C + c];
    float f0, f4, re[3], im[3];
    dft8(p, f0, f4, re, im);
    int k = r * C + c;
    int slotSz = 3 * HB * 128;
    __nv_bfloat16 hi, lo;
#define STB(s, val) { bfsplit((val), hi, lo); \
    __nv_bfloat16* b_ = Bb + (size_t)(s) * slotSz + t; \
    b_[(size_t)k * 128] = hi; b_[(size_t)(HB + k) * 128] = lo; \
    b_[(size_t)(2 * HB + k) * 128] = hi; }
    STB(0, f0); STB(1, f4);
#pragma unroll
    for (int j = 0; j < 3; j++) {
        int s = 2 + 3 * j;
        STB(s,     re[j]);           // pairs with p1 = Pr - Pi
        STB(s + 1, im[j] - re[j]);   // pairs with p2 = Pr
        STB(s + 2, re[j] + im[j]);   // pairs with p3 = Pi
    }
#undef STB
}

// ---- fused init: normalize + B DFT (3 layers) + dense B, one launch ----
__global__ void k_init(const float* __restrict__ sig, const float* __restrict__ mean,
                       const float* __restrict__ var,
                       const float* __restrict__ w0, const float* __restrict__ w1,
                       const float* __restrict__ w2, const float* __restrict__ dw) {
    int b = blockIdx.x, tid = threadIdx.x;
    if (b < 81) {
        int i = b * 256 + tid;
        if (i < NV * CIN) {
            int c = i % CIN;
            g_x[i] = (sig[i] - mean[c]) * rsqrtf(var[c]);
        }
    } else if (b < 87) {
        buildB_dev(w0, CIN, g_B + OB0, 64,  (b - 81) * 256 + tid);
    } else if (b < 283) {
        buildB_dev(w1, TT,  g_B + OB1, 512, (b - 87) * 256 + tid);
    } else if (b < 479) {
        buildB_dev(w2, TT,  g_B + OB2, 512, (b - 283) * 256 + tid);
    } else {
        int e = (b - 479) * 256 + tid;
        if (e < TT * NV) {
            int k = e / NV, n = e % NV;
            __nv_bfloat16 hi, lo; bfsplit(dw[e], hi, lo);
            g_Bd[(size_t)k * LDBD + n] = hi;
            g_Bd[(size_t)(TT + k) * LDBD + n] = lo;
            g_Bd[(size_t)(2 * TT + k) * LDBD + n] = hi;
        }
    }
}

// ---- patch gather + DFT + Karatsuba parts -> 11 A slots [Ah(512)|Al(512)] ----
__global__ void k_patch_fft(const int* __restrict__ idx,
                            const float* __restrict__ w, int C, int HB) {
    __shared__ int   sI[8][24];
    __shared__ float sW[8][24];
    int warp = threadIdx.x >> 5, lane = threadIdx.x & 31;
    int gw = blockIdx.x * 8 + warp;
    if (gw >= NV * RR) return;
    int v = gw / RR, r = gw % RR;
    if (lane < 24) {
        sI[warp][lane] = idx[gw * 24 + lane];
        sW[warp][lane] = w[gw * 24 + lane];
    }
    __syncwarp();

    int K1 = RR * C;
    __nv_bfloat16* row = g_A + (size_t)v * LDAF;

    for (int c = lane; c < C; c += 32) {
        float p[8];
#pragma unroll
        for (int a = 0; a < 8; a++) {
            p[a] = sW[warp][a*3+0] * g_x[sI[warp][a*3+0] * C + c]
                 + sW[warp][a*3+1] * g_x[sI[warp][a*3+1] * C + c]
                 + sW[warp][a*3+2] * g_x[sI[warp][a*3+2] * C + c];
        }
        float f0, f4, re[3], im[3];
        dft8(p, f0, f4, re, im);
        int k = r * C + c;
        __nv_bfloat16 hi, lo;
#define STA(s, val) { bfsplit((val), hi, lo); \
        __nv_bfloat16* a_ = row + (s) * SLOTA; \
        a_[k] = hi; a_[HB + k] = lo; }
        STA(0, f0); STA(1, f4);
#pragma unroll
        for (int j = 0; j < 3; j++) {
            int s = 2 + 3 * j;
            STA(s,     re[j] - im[j]);
            STA(s + 1, re[j]);
            STA(s + 2, im[j]);
        }
#undef STA
    }
    if (r == 0) {   // zero pads [K1,HB) in both blocks (slots shared across layers)
        __nv_bfloat16 z = __float2bfloat16(0.f);
        for (int e = K1 + lane; e < HB; e += 32)
#pragma unroll
            for (int s = 0; s < NSLOT; s++) {
                row[s * SLOTA + e] = z;
                row[s * SLOTA + HB + e] = z;
            }
    }
}

// ======== GEMM engine (96x128x64, 8 warps 2x4, warp 48x32, 3-stage ring) ========
#define ASTG 12288   // 96 rows x 128B
#define BSTG 16384   // 64 rows x 256B
#define STGSZ (ASTG + BSTG)

// ---- per-slot conv GEMM: logical K' = 3*HB, A chunks walk [Ah, Ah, Al] ----
__global__ void __launch_bounds__(256, 2)
k_gemm_f(const __nv_bfloat16* __restrict__ Ab, const __nv_bfloat16* __restrict__ Bb,
         float* __restrict__ Cb, int nh) {
    extern __shared__ char smem[];
    int sx = blockIdx.x;
    const __nv_bfloat16* A = Ab + sx * SLOTA;
    const __nv_bfloat16* B = Bb + (size_t)sx * (3 * nh * 64) * 128;

    int tid = threadIdx.x;
    int bm = blockIdx.y * 96;
    int warp = tid >> 5, lane = tid & 31;
    int wm = (warp >> 2) * 48, wn = (warp & 3) * 32;

    float acc[3][4][4];
#pragma unroll
    for (int i = 0; i < 3; i++)
#pragma unroll
        for (int j = 0; j < 4; j++)
#pragma unroll
            for (int q = 0; q < 4; q++) acc[i][j][q] = 0.f;

    auto aoffOf = [&](int c) { return ((c < nh) ? c : c - nh) * 64; };

    auto copyA = [&](int stage, int chunk) {
        char* base = smem + stage * STGSZ;
        int k0 = aoffOf(chunk);
#pragma unroll
        for (int j = 0; j < 3; j++) {        // 96 rows x 8 units = 768 = 3*256
            int idx2 = tid + 256 * j;
            int r = idx2 >> 3, u = idx2 & 7;
            int su = u ^ (r & 7);
            const __nv_bfloat16* src = A + (size_t)(bm + r) * LDAF + k0 + u * 8;
            asm volatile("cp.async.cg.shared.global [%0], [%1], 16;"
                         :: "r"(sptr(base + r * 128 + su * 16)), "l"(src));
        }
    };
    auto copyB = [&](int stage, int chunk) {
        char* base = smem + stage * STGSZ + ASTG;
        int k0 = chunk * 64;
#pragma unroll
        for (int j = 0; j < 4; j++) {        // 64 rows x 16 units = 1024 = 4*256
            int idx2 = tid + 256 * j;
            int r = idx2 >> 4, u = idx2 & 15;
            int su = (u & 8) | ((u ^ r) & 7);
            const __nv_bfloat16* src = B + (size_t)(k0 + r) * 128 + u * 8;
            asm volatile("cp.async.cg.shared.global [%0], [%1], 16;"
                         :: "r"(sptr(base + r * 256 + su * 16)), "l"(src));
        }
    };

    int niter = 3 * nh;
    copyA(0, 0);  copyB(0, 0);
    asm volatile("cp.async.commit_group;");
    copyA(1, 1);  copyB(1, 1);
    asm volatile("cp.async.commit_group;");

    int q = lane >> 3, rr = lane & 7;
    uint32_t af[2][3][4], bf2[2][4][2];

    auto ldfrag = [&](const char* sA, const char* sB, int ks, int b) {
#pragma unroll
        for (int mt = 0; mt < 3; mt++) {
            int m_loc = wm + mt * 16 + (q & 1) * 8 + rr;
            int unit = ks * 2 + (q >> 1);
            int su = unit ^ (m_loc & 7);
            asm volatile("ldmatrix.sync.aligned.m8n8.x4.shared.b16 {%0,%1,%2,%3}, [%4];"
                         : "=r"(af[b][mt][0]), "=r"(af[b][mt][1]),
                           "=r"(af[b][mt][2]), "=r"(af[b][mt][3])
                         : "r"(sptr(sA + m_loc * 128 + su * 16)));
        }
#pragma unroll
        for (int ntp = 0; ntp < 2; ntp++) {
            int k_loc = ks * 16 + (q & 1) * 8 + rr;
            int unit = (wn >> 3) + ntp * 2 + (q >> 1);
            int su = (unit & 8) | ((unit ^ k_loc) & 7);
            asm volatile("ldmatrix.sync.aligned.m8n8.x4.trans.shared.b16 {%0,%1,%2,%3}, [%4];"
                         : "=r"(bf2[b][2 * ntp][0]), "=r"(bf2[b][2 * ntp][1]),
                           "=r"(bf2[b][2 * ntp + 1][0]), "=r"(bf2[b][2 * ntp + 1][1])
                         : "r"(sptr(sB + k_loc * 256 + su * 16)));
        }
    };

    for (int i = 0; i < niter; i++) {
        asm volatile("cp.async.wait_group 1;");
        __syncthreads();
        int pf = i + 2;
        if (pf < niter) {
            int st2 = pf % 3;
            copyA(st2, pf); copyB(st2, pf);
        }
        asm volatile("cp.async.commit_group;");

        int stg = i % 3;
        const char* sA = smem + stg * STGSZ;
        const char* sB = smem + stg * STGSZ + ASTG;
        ldfrag(sA, sB, 0, 0);
#pragma unroll
        for (int ks = 0; ks < 4; ks++) {
            int cur = ks & 1;
            if (ks < 3) ldfrag(sA, sB, ks + 1, cur ^ 1);
#pragma unroll
            for (int mt = 0; mt < 3; mt++)
#pragma unroll
                for (int nt = 0; nt < 4; nt++) {
                    asm volatile(
                        "mma.sync.aligned.m16n8k16.row.col.f32.bf16.bf16.f32 "
                        "{%0,%1,%2,%3}, {%4,%5,%6,%7}, {%8,%9}, {%0,%1,%2,%3};"
                        : "+f"(acc[mt][nt][0]), "+f"(acc[mt][nt][1]),
                          "+f"(acc[mt][nt][2]), "+f"(acc[mt][nt][3])
                        : "r"(af[cur][mt][0]), "r"(af[cur][mt][1]),
                          "r"(af[cur][mt][2]), "r"(af[cur][mt][3]),
                          "r"(bf2[cur][nt][0]), "r"(bf2[cur][nt][1]));
                }
        }
    }

    int g = lane >> 2, t4 = lane & 3;
    int coff = sx * 100;   // packed g_cf slot pitch
#pragma unroll
    for (int mt = 0; mt < 3; mt++) {
#pragma unroll
        for (int nt = 0; nt < 4; nt++) {
            int lcol = wn + nt * 8 + 2 * t4;
            if (lcol >= TT) continue;
            int row0 = bm + wm + mt * 16 + g;
#pragma unroll
            for (int h = 0; h < 2; h++) {
                int r = row0 + h * 8;
                if (r >= NV) continue;
                *reinterpret_cast<float2*>(Cb + (size_t)r * LDCF + coff + lcol) =
                    make_float2(acc[mt][nt][h * 2 + 0], acc[mt][nt][h * 2 + 1]);
            }
        }
    }
}

// ---- dense GEMM (bias) ----
__global__ void __launch_bounds__(256, 2)
k_gemm(const __nv_bfloat16* __restrict__ A, int lda,
       const __nv_bfloat16* __restrict__ B, int ldb,
       const float* __restrict__ bias, int biasMod,
       float* __restrict__ C, int ldc, int M, int N, int KT) {
    extern __shared__ char smem[];
    __shared__ float sbias[128];
    int tid = threadIdx.x;
    int bm = blockIdx.y * 96, bn = blockIdx.x * 128;
    int warp = tid >> 5, lane = tid & 31;
    int wm = (warp >> 2) * 48, wn = (warp & 3) * 32;
    if (tid < 128) sbias[tid] = bias[(bn + tid) % biasMod];

    float acc[3][4][4];
#pragma unroll
    for (int i = 0; i < 3; i++)
#pragma unroll
        for (int j = 0; j < 4; j++)
#pragma unroll
            for (int q = 0; q < 4; q++) acc[i][j][q] = 0.f;

    auto copyA = [&](int stage, int k0) {
        char* base = smem + stage * STGSZ;
#pragma unroll
        for (int j = 0; j < 3; j++) {
            int idx2 = tid + 256 * j;
            int r = idx2 >> 3, u = idx2 & 7;
            int su = u ^ (r & 7);
            const __nv_bfloat16* src = A + (size_t)(bm + r) * lda + k0 + u * 8;
            asm volatile("cp.async.cg.shared.global [%0], [%1], 16;"
                         :: "r"(sptr(base + r * 128 + su * 16)), "l"(src));
        }
    };
    auto copyB = [&](int stage, int k0) {
        char* base = smem + stage * STGSZ + ASTG;
#pragma unroll
        for (int j = 0; j < 4; j++) {
            int idx2 = tid + 256 * j;
            int r = idx2 >> 4, u = idx2 & 15;
            int su = (u & 8) | ((u ^ r) & 7);
            const __nv_bfloat16* src = B + (size_t)(k0 + r) * ldb + bn + u * 8;
            asm volatile("cp.async.cg.shared.global [%0], [%1], 16;"
                         :: "r"(sptr(base + r * 256 + su * 16)), "l"(src));
        }
    };

    int niter = KT >> 6;
    copyA(0, 0);  copyB(0, 0);
    asm volatile("cp.async.commit_group;");
    copyA(1, 64); copyB(1, 64);
    asm volatile("cp.async.commit_group;");

    int q = lane >> 3, rr = lane & 7;
    uint32_t af[2][3][4], bf2[2][4][2];
    auto ldfrag = [&](const char* sA, const char* sB, int ks, int b) {
#pragma unroll
        for (int mt = 0; mt < 3; mt++) {
            int m_loc = wm + mt * 16 + (q & 1) * 8 + rr;
            int unit = ks * 2 + (q >> 1);
            int su = unit ^ (m_loc & 7);
            asm volatile("ldmatrix.sync.aligned.m8n8.x4.shared.b16 {%0,%1,%2,%3}, [%4];"
                         : "=r"(af[b][mt][0]), "=r"(af[b][mt][1]),
                           "=r"(af[b][mt][2]), "=r"(af[b][mt][3])
                         : "r"(sptr(sA + m_loc * 128 + su * 16)));
        }
#pragma unroll
        for (int ntp = 0; ntp < 2; ntp++) {
            int k_loc = ks * 16 + (q & 1) * 8 + rr;
            int unit = (wn >> 3) + ntp * 2 + (q >> 1);
            int su = (unit & 8) | ((unit ^ k_loc) & 7);
            asm volatile("ldmatrix.sync.aligned.m8n8.x4.trans.shared.b16 {%0,%1,%2,%3}, [%4];"
                         : "=r"(bf2[b][2 * ntp][0]), "=r"(bf2[b][2 * ntp][1]),
                           "=r"(bf2[b][2 * ntp + 1][0]), "=r"(bf2[b][2 * ntp + 1][1])
                         : "r"(sptr(sB + k_loc * 256 + su * 16)));
        }
    };

    for (int i = 0; i < niter; i++) {
        asm volatile("cp.async.wait_group 1;");
        __syncthreads();
        int pf = i + 2;
        if (pf < niter) {
            int st2 = pf % 3;
            copyA(st2, pf * 64); copyB(st2, pf * 64);
        }
        asm volatile("cp.async.commit_group;");
        int stg = i % 3;
        const char* sA = smem + stg * STGSZ;
        const char* sB = smem + stg * STGSZ + ASTG;
        ldfrag(sA, sB, 0, 0);
#pragma unroll
        for (int ks = 0; ks < 4; ks++) {
            int cur = ks & 1;
            if (ks < 3) ldfrag(sA, sB, ks + 1, cur ^ 1);
#pragma unroll
            for (int mt = 0; mt < 3; mt++)
#pragma unroll
                for (int nt = 0; nt < 4; nt++) {
                    asm volatile(
                        "mma.sync.aligned.m16n8k16.row.col.f32.bf16.bf16.f32 "
                        "{%0,%1,%2,%3}, {%4,%5,%6,%7}, {%8,%9}, {%0,%1,%2,%3};"
                        : "+f"(acc[mt][nt][0]), "+f"(acc[mt][nt][1]),
                          "+f"(acc[mt][nt][2]), "+f"(acc[mt][nt][3])
                        : "r"(af[cur][mt][0]), "r"(af[cur][mt][1]),
                          "r"(af[cur][mt][2]), "r"(af[cur][mt][3]),
                          "r"(bf2[cur][nt][0]), "r"(bf2[cur][nt][1]));
                }
        }
    }

    int g = lane >> 2, t4 = lane & 3;
#pragma unroll
    for (int mt = 0; mt < 3; mt++) {
#pragma unroll
        for (int nt = 0; nt < 4; nt++) {
            int lcol = wn + nt * 8 + 2 * t4;
            int col = bn + lcol;
            if (col >= N) continue;
            float b0 = sbias[lcol], b1 = sbias[lcol + 1];
            int row0 = bm + wm + mt * 16 + g;
#pragma unroll
            for (int h = 0; h < 2; h++) {
                int r = row0 + h * 8;
                if (r >= M) continue;
                *reinterpret_cast<float2*>(C + (size_t)r * ldc + col) =
                    make_float2(acc[mt][nt][h * 2 + 0] + b0, acc[mt][nt][h * 2 + 1] + b1);
            }
        }
    }
}

// ---- Karatsuba combine + IDFT + bias + relu + AMP + BN -> g_x, g_Ax ----
__device__ __constant__ float c_COS8[8] = {1.f, SQH, 0.f, -SQH, -1.f, -SQH, 0.f, SQH};
__device__ __constant__ float c_SIN8[8] = {0.f, SQH, 1.f, SQH, 0.f, -SQH, -1.f, -SQH};

__global__ void k_amp_fft(const float* __restrict__ bias,
                          const float* __restrict__ bn_g, const float* __restrict__ bn_b,
                          const float* __restrict__ bn_m, const float* __restrict__ bn_v,
                          int blk) {
    int v = blockIdx.x;
    int tid = threadIdx.x, lane = tid & 31, warp = tid >> 5;
    const float* row = g_cf + (size_t)v * LDCF;
    __shared__ float wsum[4][8];
    __shared__ int snbest;

    float y[8];
#pragma unroll
    for (int n = 0; n < 8; n++) y[n] = 0.f;
    if (tid < TT) {
        float c0 = row[tid], c4 = row[100 + tid];
        float Cr[3], Ci[3];
#pragma unroll
        for (int j = 0; j < 3; j++) {
            int base = (2 + 3 * j) * 100;
            float g1 = row[base + tid], g2 = row[base + 100 + tid], g3 = row[base + 200 + tid];
            Cr[j] = g1 + g3;
            Ci[j] = g1 + g2;
        }
        float b = bias[tid];
#pragma unroll
        for (int n = 0; n < 8; n++) {
            float s = c0 + ((n & 1) ? -c4 : c4)
                + 2.f * (Cr[0] * c_COS8[n & 7]     - Ci[0] * c_SIN8[n & 7]
                       + Cr[1] * c_COS8[(2*n) & 7] - Ci[1] * c_SIN8[(2*n) & 7]
                       + Cr[2] * c_COS8[(3*n) & 7] - Ci[2] * c_SIN8[(3*n) & 7]);
            y[n] = fmaxf(0.125f * s + b, 0.f);
        }
    }
    float sq[8];
#pragma unroll
    for (int n = 0; n < 8; n++) {
        sq[n] = y[n] * y[n];
#pragma unroll
        for (int o = 16; o; o >>= 1) sq[n] += __shfl_down_sync(0xffffffffu, sq[n], o);
    }
    if (lane == 0)
#pragma unroll
        for (int n = 0; n < 8; n++) wsum[warp][n] = sq[n];
    __syncthreads();
    if (tid == 0) {
        int best = 0; float bv = -1.f;
#pragma unroll
        for (int n = 0; n < 8; n++) {
            float s = wsum[0][n] + wsum[1][n] + wsum[2][n] + wsum[3][n];
            if (s > bv) { bv = s; best = n; }
        }
        snbest = best;
    }
    __syncthreads();
    if (tid < TT) {
        int b = snbest;
        float x = y[0];
#pragma unroll
        for (int n = 1; n < 8; n++) if (b == n) x = y[n];
        float gg = bn_g[blk * TT + tid], bb = bn_b[blk * TT + tid];
        float mm = bn_m[blk * TT + tid], va = bn_v[blk * TT + tid];
        float yy = gg * (x - mm) * rsqrtf(va + 1e-3f) + bb;
        g_x[(size_t)v * TT + tid] = yy;
        __nv_bfloat16 hi, lo; bfsplit(yy, hi, lo);
        __nv_bfloat16* arow = g_Ax + (size_t)v * LDAX;
        arow[tid] = hi; arow[TT + tid] = hi; arow[2 * TT + tid] = lo;
    }
}

extern "C" void kernel_launch(void* const* d_in, const int* in_sizes, int n_in,
                              void* d_out, int out_size) {
    const float* signal  = (const float*)d_in[0];
    const int*   bc_idx  = (const int*)  d_in[1];
    const float* bc_w    = (const float*)d_in[2];
    const float* nmean   = (const float*)d_in[3];
    const float* nvar    = (const float*)d_in[4];
    const float* w0      = (const float*)d_in[5];
    const float* b0      = (const float*)d_in[6];
    const float* w1      = (const float*)d_in[7];
    const float* b1      = (const float*)d_in[8];
    const float* w2      = (const float*)d_in[9];
    const float* b2      = (const float*)d_in[10];
    const float* bn_g    = (const float*)d_in[11];
    const float* bn_b    = (const float*)d_in[12];
    const float* bn_m    = (const float*)d_in[13];
    const float* bn_v    = (const float*)d_in[14];
    const float* dense_w = (const float*)d_in[15];
    const float* dense_b = (const float*)d_in[16];
    float* out = (float*)d_out;

    const int SMEM = 3 * STGSZ;   // 84KB
    cudaFuncSetAttribute(k_gemm_f, cudaFuncAttributeMaxDynamicSharedMemorySize, SMEM);
    cudaFuncSetAttribute(k_gemm,   cudaFuncAttributeMaxDynamicSharedMemorySize, SMEM);

    __nv_bfloat16 *p_A, *p_B, *p_Ax, *p_Bd;
    float *p_cf;
    cudaGetSymbolAddress((void**)&p_A, g_A);
    cudaGetSymbolAddress((void**)&p_B, g_B);
    cudaGetSymbolAddress((void**)&p_Ax, g_Ax);
    cudaGetSymbolAddress((void**)&p_Bd, g_Bd);
    cudaGetSymbolAddress((void**)&p_cf, g_cf);

    k_init<<<3171, 256>>>(signal, nmean, nvar, w0, w1, w2, dense_w);

    const float* bs[3] = {b0, b1, b2};
    const int    Cs[3] = {CIN, TT, TT};
    const int    HBs[3] = {64, 512, 512};
    const size_t OBs[3] = {OB0, OB1, OB2};

    for (int blk = 0; blk < 3; blk++) {
        k_patch_fft<<<(NV * RR + 7) / 8, 256>>>(bc_idx, bc_w, Cs[blk], HBs[blk]);
        k_gemm_f<<<dim3(NSLOT, MP / 96), 256, SMEM>>>(p_A, p_B + OBs[blk], p_cf, HBs[blk] / 64);
        k_amp_fft<<<NV, 128>>>(bs[blk], bn_g, bn_b, bn_m, bn_v, blk);
    }

    // dense head
    dim3 denseGrid(54, MP / 96);
    k_gemm<<<denseGrid, 256, SMEM>>>(p_Ax, LDAX, p_Bd, LDBD, dense_b, NV,
                                     out, NV, NV, NV, KT_DENSE);
}

// round 16
// speedup vs baseline: 1.1536x; 1.0680x over previous
#include <cuda_runtime.h>
#include <cuda_bf16.h>
#include <cuda_fp16.h>
#include <math.h>
#include <stdint.h>

#define NV 6890
#define MP 6912
#define CIN 3
#define RR 5
#define AA 8
#define TT 100
#define NSLOT 11
#define SLOTA 1024                 // A slot stride: [Ah | Al], each padded to 512
#define LDAF (NSLOT * SLOTA)       // 11264
#define LDCF 1104                  // g_cf row stride (floats): 11 slots x 100, +4 pad
#define LDAX 128                   // dense A' row stride (fp16, K=100 padded to 128)
#define LDBD 6912
#define KT_DENSE 128
// B regions (elems): layer0 11*3*64*128, layers1/2 11*3*512*128 each
#define OB0 0
#define OB1 270336
#define OB2 2433024
#define BTOT 4595712

// ---- scratch (device globals, zero-initialized at module load) ----
__device__ float g_x[NV * TT];
__device__ __nv_bfloat16 g_A [(size_t)MP * LDAF];
__device__ __nv_bfloat16 g_B [BTOT];
__device__ __half g_Ax[(size_t)MP * LDAX];          // dense input, fp16, pads stay 0
__device__ __half g_Bd[(size_t)KT_DENSE * LDBD];    // dense weights, fp16, pad rows stay 0
__device__ float g_cf[(size_t)NV * LDCF];

__device__ __forceinline__ void bfsplit(float f, __nv_bfloat16& hi, __nv_bfloat16& lo) {
    hi = __float2bfloat16(f);
    lo = __float2bfloat16(f - __bfloat162float(hi));
}
__device__ __forceinline__ uint32_t sptr(const void* p) {
    return (uint32_t)__cvta_generic_to_shared(p);
}

#define SQH 0.70710678118654752f

// ---- 8-pt DFT: p[8] -> f0, f4, (re,im) for f=1,2,3 ----
__device__ __forceinline__ void dft8(const float* p, float& f0, float& f4,
                                     float* re, float* im) {
    float s07 = p[1] - p[3] - p[5] + p[7];
    float s25 = p[1] + p[3] - p[5] - p[7];
    float s16 = p[2] - p[6];
    float d04 = p[0] - p[4];
    f0 = p[0]+p[1]+p[2]+p[3]+p[4]+p[5]+p[6]+p[7];
    f4 = p[0]-p[1]+p[2]-p[3]+p[4]-p[5]+p[6]-p[7];
    re[0] = d04 + SQH * s07;        im[0] = -(SQH * s25 + s16);
    re[1] = p[0]-p[2]+p[4]-p[6];    im[1] = -(p[1]-p[3]+p[5]-p[7]);
    re[2] = d04 - SQH * s07;        im[2] = s16 - SQH * s25;
}

// ---- weight DFT -> B slot rows [Bh @k | Bl @HB+k | Bh @2HB+k], Karatsuba combos ----
__device__ void buildB_dev(const float* __restrict__ W, int C,
                           __nv_bfloat16* __restrict__ Bb, int HB, int e) {
    int tot = TT * RR * C;
    if (e >= tot) return;
    int t = e / (RR * C);
    int rc = e % (RR * C);
    int r = rc / C, c = rc % C;
    float p[8];
#pragma unroll
    for (int a = 0; a < 8; a++)
        p[a] = W[(((size_t)t * RR + r) * AA + a) * C + c];
    float f0, f4, re[3], im[3];
    dft8(p, f0, f4, re, im);
    int k = r * C + c;
    int slotSz = 3 * HB * 128;
    __nv_bfloat16 hi, lo;
#define STB(s, val) { bfsplit((val), hi, lo); \
    __nv_bfloat16* b_ = Bb + (size_t)(s) * slotSz + t; \
    b_[(size_t)k * 128] = hi; b_[(size_t)(HB + k) * 128] = lo; \
    b_[(size_t)(2 * HB + k) * 128] = hi; }
    STB(0, f0); STB(1, f4);
#pragma unroll
    for (int j = 0; j < 3; j++) {
        int s = 2 + 3 * j;
        STB(s,     re[j]);           // pairs with p1 = Pr - Pi
        STB(s + 1, im[j] - re[j]);   // pairs with p2 = Pr
        STB(s + 2, re[j] + im[j]);   // pairs with p3 = Pi
    }
#undef STB
}

// ---- fused init: normalize + B DFT (3 layers) + dense B (fp16), one launch ----
__global__ void k_init(const float* __restrict__ sig, const float* __restrict__ mean,
                       const float* __restrict__ var,
                       const float* __restrict__ w0, const float* __restrict__ w1,
                       const float* __restrict__ w2, const float* __restrict__ dw) {
    int b = blockIdx.x, tid = threadIdx.x;
    if (b < 81) {
        int i = b * 256 + tid;
        if (i < NV * CIN) {
            int c = i % CIN;
            g_x[i] = (sig[i] - mean[c]) * rsqrtf(var[c]);
        }
    } else if (b < 87) {
        buildB_dev(w0, CIN, g_B + OB0, 64,  (b - 81) * 256 + tid);
    } else if (b < 283) {
        buildB_dev(w1, TT,  g_B + OB1, 512, (b - 87) * 256 + tid);
    } else if (b < 479) {
        buildB_dev(w2, TT,  g_B + OB2, 512, (b - 283) * 256 + tid);
    } else {
        int e = (b - 479) * 256 + tid;
        if (e < TT * NV) {
            int k = e / NV, n = e % NV;
            g_Bd[(size_t)k * LDBD + n] = __float2half(dw[e]);  // row stride LDBD!
        }
    }
}

// ---- patch gather + DFT + Karatsuba parts -> 11 A slots [Ah(512)|Al(512)] ----
__global__ void k_patch_fft(const int* __restrict__ idx,
                            const float* __restrict__ w, int C, int HB) {
    __shared__ int   sI[8][24];
    __shared__ float sW[8][24];
    int warp = threadIdx.x >> 5, lane = threadIdx.x & 31;
    int gw = blockIdx.x * 8 + warp;
    if (gw >= NV * RR) return;
    int v = gw / RR, r = gw % RR;
    if (lane < 24) {
        sI[warp][lane] = idx[gw * 24 + lane];
        sW[warp][lane] = w[gw * 24 + lane];
    }
    __syncwarp();

    int K1 = RR * C;
    __nv_bfloat16* row = g_A + (size_t)v * LDAF;

    for (int c = lane; c < C; c += 32) {
        float p[8];
#pragma unroll
        for (int a = 0; a < 8; a++) {
            p[a] = sW[warp][a*3+0] * g_x[sI[warp][a*3+0] * C + c]
                 + sW[warp][a*3+1] * g_x[sI[warp][a*3+1] * C + c]
                 + sW[warp][a*3+2] * g_x[sI[warp][a*3+2] * C + c];
        }
        float f0, f4, re[3], im[3];
        dft8(p, f0, f4, re, im);
        int k = r * C + c;
        __nv_bfloat16 hi, lo;
#define STA(s, val) { bfsplit((val), hi, lo); \
        __nv_bfloat16* a_ = row + (s) * SLOTA; \
        a_[k] = hi; a_[HB + k] = lo; }
        STA(0, f0); STA(1, f4);
#pragma unroll
        for (int j = 0; j < 3; j++) {
            int s = 2 + 3 * j;
            STA(s,     re[j] - im[j]);
            STA(s + 1, re[j]);
            STA(s + 2, im[j]);
        }
#undef STA
    }
    if (r == 0) {   // zero pads [K1,HB) in both blocks (slots shared across layers)
        __nv_bfloat16 z = __float2bfloat16(0.f);
        for (int e = K1 + lane; e < HB; e += 32)
#pragma unroll
            for (int s = 0; s < NSLOT; s++) {
                row[s * SLOTA + e] = z;
                row[s * SLOTA + HB + e] = z;
            }
    }
}

// ======== GEMM engine (96x128x64, 8 warps 2x4, warp 48x32, 3-stage ring) ========
#define ASTG 12288   // 96 rows x 128B
#define BSTG 16384   // 64 rows x 256B
#define STGSZ (ASTG + BSTG)

// ---- per-slot conv GEMM (bf16x3): logical K' = 3*HB, A chunks walk [Ah, Ah, Al] ----
__global__ void __launch_bounds__(256, 2)
k_gemm_f(const __nv_bfloat16* __restrict__ Ab, const __nv_bfloat16* __restrict__ Bb,
         float* __restrict__ Cb, int nh) {
    extern __shared__ char smem[];
    int sx = blockIdx.x;
    const __nv_bfloat16* A = Ab + sx * SLOTA;
    const __nv_bfloat16* B = Bb + (size_t)sx * (3 * nh * 64) * 128;

    int tid = threadIdx.x;
    int bm = blockIdx.y * 96;
    int warp = tid >> 5, lane = tid & 31;
    int wm = (warp >> 2) * 48, wn = (warp & 3) * 32;

    float acc[3][4][4];
#pragma unroll
    for (int i = 0; i < 3; i++)
#pragma unroll
        for (int j = 0; j < 4; j++)
#pragma unroll
            for (int q = 0; q < 4; q++) acc[i][j][q] = 0.f;

    auto aoffOf = [&](int c) { return ((c < nh) ? c : c - nh) * 64; };

    auto copyA = [&](int stage, int chunk) {
        char* base = smem + stage * STGSZ;
        int k0 = aoffOf(chunk);
#pragma unroll
        for (int j = 0; j < 3; j++) {
            int idx2 = tid + 256 * j;
            int r = idx2 >> 3, u = idx2 & 7;
            int su = u ^ (r & 7);
            const __nv_bfloat16* src = A + (size_t)(bm + r) * LDAF + k0 + u * 8;
            asm volatile("cp.async.cg.shared.global [%0], [%1], 16;"
                         :: "r"(sptr(base + r * 128 + su * 16)), "l"(src));
        }
    };
    auto copyB = [&](int stage, int chunk) {
        char* base = smem + stage * STGSZ + ASTG;
        int k0 = chunk * 64;
#pragma unroll
        for (int j = 0; j < 4; j++) {
            int idx2 = tid + 256 * j;
            int r = idx2 >> 4, u = idx2 & 15;
            int su = (u & 8) | ((u ^ r) & 7);
            const __nv_bfloat16* src = B + (size_t)(k0 + r) * 128 + u * 8;
            asm volatile("cp.async.cg.shared.global [%0], [%1], 16;"
                         :: "r"(sptr(base + r * 256 + su * 16)), "l"(src));
        }
    };

    int niter = 3 * nh;
    copyA(0, 0);  copyB(0, 0);
    asm volatile("cp.async.commit_group;");
    copyA(1, 1);  copyB(1, 1);
    asm volatile("cp.async.commit_group;");

    int q = lane >> 3, rr = lane & 7;
    uint32_t af[2][3][4], bf2[2][4][2];

    auto ldfrag = [&](const char* sA, const char* sB, int ks, int b) {
#pragma unroll
        for (int mt = 0; mt < 3; mt++) {
            int m_loc = wm + mt * 16 + (q & 1) * 8 + rr;
            int unit = ks * 2 + (q >> 1);
            int su = unit ^ (m_loc & 7);
            asm volatile("ldmatrix.sync.aligned.m8n8.x4.shared.b16 {%0,%1,%2,%3}, [%4];"
                         : "=r"(af[b][mt][0]), "=r"(af[b][mt][1]),
                           "=r"(af[b][mt][2]), "=r"(af[b][mt][3])
                         : "r"(sptr(sA + m_loc * 128 + su * 16)));
        }
#pragma unroll
        for (int ntp = 0; ntp < 2; ntp++) {
            int k_loc = ks * 16 + (q & 1) * 8 + rr;
            int unit = (wn >> 3) + ntp * 2 + (q >> 1);
            int su = (unit & 8) | ((unit ^ k_loc) & 7);
            asm volatile("ldmatrix.sync.aligned.m8n8.x4.trans.shared.b16 {%0,%1,%2,%3}, [%4];"
                         : "=r"(bf2[b][2 * ntp][0]), "=r"(bf2[b][2 * ntp][1]),
                           "=r"(bf2[b][2 * ntp + 1][0]), "=r"(bf2[b][2 * ntp + 1][1])
                         : "r"(sptr(sB + k_loc * 256 + su * 16)));
        }
    };

    for (int i = 0; i < niter; i++) {
        asm volatile("cp.async.wait_group 1;");
        __syncthreads();
        int pf = i + 2;
        if (pf < niter) {
            int st2 = pf % 3;
            copyA(st2, pf); copyB(st2, pf);
        }
        asm volatile("cp.async.commit_group;");

        int stg = i % 3;
        const char* sA = smem + stg * STGSZ;
        const char* sB = smem + stg * STGSZ + ASTG;
        ldfrag(sA, sB, 0, 0);
#pragma unroll
        for (int ks = 0; ks < 4; ks++) {
            int cur = ks & 1;
            if (ks < 3) ldfrag(sA, sB, ks + 1, cur ^ 1);
#pragma unroll
            for (int mt = 0; mt < 3; mt++)
#pragma unroll
                for (int nt = 0; nt < 4; nt++) {
                    asm volatile(
                        "mma.sync.aligned.m16n8k16.row.col.f32.bf16.bf16.f32 "
                        "{%0,%1,%2,%3}, {%4,%5,%6,%7}, {%8,%9}, {%0,%1,%2,%3};"
                        : "+f"(acc[mt][nt][0]), "+f"(acc[mt][nt][1]),
                          "+f"(acc[mt][nt][2]), "+f"(acc[mt][nt][3])
                        : "r"(af[cur][mt][0]), "r"(af[cur][mt][1]),
                          "r"(af[cur][mt][2]), "r"(af[cur][mt][3]),
                          "r"(bf2[cur][nt][0]), "r"(bf2[cur][nt][1]));
                }
        }
    }

    int g = lane >> 2, t4 = lane & 3;
    int coff = sx * 100;   // packed g_cf slot pitch
#pragma unroll
    for (int mt = 0; mt < 3; mt++) {
#pragma unroll
        for (int nt = 0; nt < 4; nt++) {
            int lcol = wn + nt * 8 + 2 * t4;
            if (lcol >= TT) continue;
            int row0 = bm + wm + mt * 16 + g;
#pragma unroll
            for (int h = 0; h < 2; h++) {
                int r = row0 + h * 8;
                if (r >= NV) continue;
                *reinterpret_cast<float2*>(Cb + (size_t)r * LDCF + coff + lcol) =
                    make_float2(acc[mt][nt][h * 2 + 0], acc[mt][nt][h * 2 + 1]);
            }
        }
    }
}

// ---- dense GEMM (fp16 single-term, bias) ----
__global__ void __launch_bounds__(256, 2)
k_gemm_d(const __half* __restrict__ A, int lda,
         const __half* __restrict__ B, int ldb,
         const float* __restrict__ bias,
         float* __restrict__ C, int ldc, int M, int N, int KT) {
    extern __shared__ char smem[];
    __shared__ float sbias[128];
    int tid = threadIdx.x;
    int bm = blockIdx.y * 96, bn = blockIdx.x * 128;
    int warp = tid >> 5, lane = tid & 31;
    int wm = (warp >> 2) * 48, wn = (warp & 3) * 32;
    if (tid < 128) sbias[tid] = bias[(bn + tid) % NV];

    float acc[3][4][4];
#pragma unroll
    for (int i = 0; i < 3; i++)
#pragma unroll
        for (int j = 0; j < 4; j++)
#pragma unroll
            for (int q = 0; q < 4; q++) acc[i][j][q] = 0.f;

    auto copyA = [&](int stage, int k0) {
        char* base = smem + stage * STGSZ;
#pragma unroll
        for (int j = 0; j < 3; j++) {
            int idx2 = tid + 256 * j;
            int r = idx2 >> 3, u = idx2 & 7;
            int su = u ^ (r & 7);
            const __half* src = A + (size_t)(bm + r) * lda + k0 + u * 8;
            asm volatile("cp.async.cg.shared.global [%0], [%1], 16;"
                         :: "r"(sptr(base + r * 128 + su * 16)), "l"(src));
        }
    };
    auto copyB = [&](int stage, int k0) {
        char* base = smem + stage * STGSZ + ASTG;
#pragma unroll
        for (int j = 0; j < 4; j++) {
            int idx2 = tid + 256 * j;
            int r = idx2 >> 4, u = idx2 & 15;
            int su = (u & 8) | ((u ^ r) & 7);
            const __half* src = B + (size_t)(k0 + r) * ldb + bn + u * 8;
            asm volatile("cp.async.cg.shared.global [%0], [%1], 16;"
                         :: "r"(sptr(base + r * 256 + su * 16)), "l"(src));
        }
    };

    int niter = KT >> 6;   // 2
    copyA(0, 0);  copyB(0, 0);
    asm volatile("cp.async.commit_group;");
    copyA(1, 64); copyB(1, 64);
    asm volatile("cp.async.commit_group;");

    int q = lane >> 3, rr = lane & 7;
    uint32_t af[2][3][4], bf2[2][4][2];
    auto ldfrag = [&](const char* sA, const char* sB, int ks, int b) {
#pragma unroll
        for (int mt = 0; mt < 3; mt++) {
            int m_loc = wm + mt * 16 + (q & 1) * 8 + rr;
            int unit = ks * 2 + (q >> 1);
            int su = unit ^ (m_loc & 7);
            asm volatile("ldmatrix.sync.aligned.m8n8.x4.shared.b16 {%0,%1,%2,%3}, [%4];"
                         : "=r"(af[b][mt][0]), "=r"(af[b][mt][1]),
                           "=r"(af[b][mt][2]), "=r"(af[b][mt][3])
                         : "r"(sptr(sA + m_loc * 128 + su * 16)));
        }
#pragma unroll
        for (int ntp = 0; ntp < 2; ntp++) {
            int k_loc = ks * 16 + (q & 1) * 8 + rr;
            int unit = (wn >> 3) + ntp * 2 + (q >> 1);
            int su = (unit & 8) | ((unit ^ k_loc) & 7);
            asm volatile("ldmatrix.sync.aligned.m8n8.x4.trans.shared.b16 {%0,%1,%2,%3}, [%4];"
                         : "=r"(bf2[b][2 * ntp][0]), "=r"(bf2[b][2 * ntp][1]),
                           "=r"(bf2[b][2 * ntp + 1][0]), "=r"(bf2[b][2 * ntp + 1][1])
                         : "r"(sptr(sB + k_loc * 256 + su * 16)));
        }
    };

    for (int i = 0; i < niter; i++) {
        asm volatile("cp.async.wait_group 1;");
        __syncthreads();
        int pf = i + 2;
        if (pf < niter) {
            int st2 = pf % 3;
            copyA(st2, pf * 64); copyB(st2, pf * 64);
        }
        asm volatile("cp.async.commit_group;");
        int stg = i % 3;
        const char* sA = smem + stg * STGSZ;
        const char* sB = smem + stg * STGSZ + ASTG;
        ldfrag(sA, sB, 0, 0);
#pragma unroll
        for (int ks = 0; ks < 4; ks++) {
            int cur = ks & 1;
            if (ks < 3) ldfrag(sA, sB, ks + 1, cur ^ 1);
#pragma unroll
            for (int mt = 0; mt < 3; mt++)
#pragma unroll
                for (int nt = 0; nt < 4; nt++) {
                    asm volatile(
                        "mma.sync.aligned.m16n8k16.row.col.f32.f16.f16.f32 "
                        "{%0,%1,%2,%3}, {%4,%5,%6,%7}, {%8,%9}, {%0,%1,%2,%3};"
                        : "+f"(acc[mt][nt][0]), "+f"(acc[mt][nt][1]),
                          "+f"(acc[mt][nt][2]), "+f"(acc[mt][nt][3])
                        : "r"(af[cur][mt][0]), "r"(af[cur][mt][1]),
                          "r"(af[cur][mt][2]), "r"(af[cur][mt][3]),
                          "r"(bf2[cur][nt][0]), "r"(bf2[cur][nt][1]));
                }
        }
    }

    int g = lane >> 2, t4 = lane & 3;
#pragma unroll
    for (int mt = 0; mt < 3; mt++) {
#pragma unroll
        for (int nt = 0; nt < 4; nt++) {
            int lcol = wn + nt * 8 + 2 * t4;
            int col = bn + lcol;
            if (col >= N) continue;
            float b0 = sbias[lcol], b1 = sbias[lcol + 1];
            int row0 = bm + wm + mt * 16 + g;
#pragma unroll
            for (int h = 0; h < 2; h++) {
                int r = row0 + h * 8;
                if (r >= M) continue;
                *reinterpret_cast<float2*>(C + (size_t)r * ldc + col) =
                    make_float2(acc[mt][nt][h * 2 + 0] + b0, acc[mt][nt][h * 2 + 1] + b1);
            }
        }
    }
}

// ---- Karatsuba combine + IDFT + bias + relu + AMP + BN -> g_x, g_Ax ----
__device__ __constant__ float c_COS8[8] = {1.f, SQH, 0.f, -SQH, -1.f, -SQH, 0.f, SQH};
__device__ __constant__ float c_SIN8[8] = {0.f, SQH, 1.f, SQH, 0.f, -SQH, -1.f, -SQH};

__global__ void k_amp_fft(const float* __restrict__ bias,
                          const float* __restrict__ bn_g, const float* __restrict__ bn_b,
                          const float* __restrict__ bn_m, const float* __restrict__ bn_v,
                          int blk) {
    int v = blockIdx.x;
    int tid = threadIdx.x, lane = tid & 31, warp = tid >> 5;
    const float* row = g_cf + (size_t)v * LDCF;
    __shared__ float wsum[4][8];
    __shared__ int snbest;

    float y[8];
#pragma unroll
    for (int n = 0; n < 8; n++) y[n] = 0.f;
    if (tid < TT) {
        float c0 = row[tid], c4 = row[100 + tid];
        float Cr[3], Ci[3];
#pragma unroll
        for (int j = 0; j < 3; j++) {
            int base = (2 + 3 * j) * 100;
            float g1 = row[base + tid], g2 = row[base + 100 + tid], g3 = row[base + 200 + tid];
            Cr[j] = g1 + g3;
            Ci[j] = g1 + g2;
        }
        float b = bias[tid];
#pragma unroll
        for (int n = 0; n < 8; n++) {
            float s = c0 + ((n & 1) ? -c4 : c4)
                + 2.f * (Cr[0] * c_COS8[n & 7]     - Ci[0] * c_SIN8[n & 7]
                       + Cr[1] * c_COS8[(2*n) & 7] - Ci[1] * c_SIN8[(2*n) & 7]
                       + Cr[2] * c_COS8[(3*n) & 7] - Ci[2] * c_SIN8[(3*n) & 7]);
            y[n] = fmaxf(0.125f * s + b, 0.f);
        }
    }
    float sq[8];
#pragma unroll
    for (int n = 0; n < 8; n++) {
        sq[n] = y[n] * y[n];
#pragma unroll
        for (int o = 16; o; o >>= 1) sq[n] += __shfl_down_sync(0xffffffffu, sq[n], o);
    }
    if (lane == 0)
#pragma unroll
        for (int n = 0; n < 8; n++) wsum[warp][n] = sq[n];
    __syncthreads();
    if (tid == 0) {
        int best = 0; float bv = -1.f;
#pragma unroll
        for (int n = 0; n < 8; n++) {
            float s = wsum[0][n] + wsum[1][n] + wsum[2][n] + wsum[3][n];
            if (s > bv) { bv = s; best = n; }
        }
        snbest = best;
    }
    __syncthreads();
    if (tid < TT) {
        int b = snbest;
        float x = y[0];
#pragma unroll
        for (int n = 1; n < 8; n++) if (b == n) x = y[n];
        float gg = bn_g[blk * TT + tid], bb = bn_b[blk * TT + tid];
        float mm = bn_m[blk * TT + tid], va = bn_v[blk * TT + tid];
        float yy = gg * (x - mm) * rsqrtf(va + 1e-3f) + bb;
        g_x[(size_t)v * TT + tid] = yy;
        g_Ax[(size_t)v * LDAX + tid] = __float2half(yy);
    }
}

extern "C" void kernel_launch(void* const* d_in, const int* in_sizes, int n_in,
                              void* d_out, int out_size) {
    const float* signal  = (const float*)d_in[0];
    const int*   bc_idx  = (const int*)  d_in[1];
    const float* bc_w    = (const float*)d_in[2];
    const float* nmean   = (const float*)d_in[3];
    const float* nvar    = (const float*)d_in[4];
    const float* w0      = (const float*)d_in[5];
    const float* b0      = (const float*)d_in[6];
    const float* w1      = (const float*)d_in[7];
    const float* b1      = (const float*)d_in[8];
    const float* w2      = (const float*)d_in[9];
    const float* b2      = (const float*)d_in[10];
    const float* bn_g    = (const float*)d_in[11];
    const float* bn_b    = (const float*)d_in[12];
    const float* bn_m    = (const float*)d_in[13];
    const float* bn_v    = (const float*)d_in[14];
    const float* dense_w = (const float*)d_in[15];
    const float* dense_b = (const float*)d_in[16];
    float* out = (float*)d_out;

    const int SMEM = 3 * STGSZ;   // 84KB
    cudaFuncSetAttribute(k_gemm_f, cudaFuncAttributeMaxDynamicSharedMemorySize, SMEM);
    cudaFuncSetAttribute(k_gemm_d, cudaFuncAttributeMaxDynamicSharedMemorySize, SMEM);

    __nv_bfloat16 *p_A, *p_B;
    __half *p_Ax, *p_Bd;
    float *p_cf;
    cudaGetSymbolAddress((void**)&p_A, g_A);
    cudaGetSymbolAddress((void**)&p_B, g_B);
    cudaGetSymbolAddress((void**)&p_Ax, g_Ax);
    cudaGetSymbolAddress((void**)&p_Bd, g_Bd);
    cudaGetSymbolAddress((void**)&p_cf, g_cf);

    k_init<<<3171, 256>>>(signal, nmean, nvar, w0, w1, w2, dense_w);

    const float* bs[3] = {b0, b1, b2};
    const int    Cs[3] = {CIN, TT, TT};
    const int    HBs[3] = {64, 512, 512};
    const size_t OBs[3] = {OB0, OB1, OB2};

    for (int blk = 0; blk < 3; blk++) {
        k_patch_fft<<<(NV * RR + 7) / 8, 256>>>(bc_idx, bc_w, Cs[blk], HBs[blk]);
        k_gemm_f<<<dim3(NSLOT, MP / 96), 256, SMEM>>>(p_A, p_B + OBs[blk], p_cf, HBs[blk] / 64);
        k_amp_fft<<<NV, 128>>>(bs[blk], bn_g, bn_b, bn_m, bn_v, blk);
    }

    // dense head (fp16 single-term)
    dim3 denseGrid(54, MP / 96);
    k_gemm_d<<<denseGrid, 256, SMEM>>>(p_Ax, LDAX, p_Bd, LDBD, dense_b,
                                       out, NV, NV, NV, KT_DENSE);
}